// round 1
// baseline (speedup 1.0000x reference)
#include <cuda_runtime.h>
#include <math.h>

// Problem constants
#define Cc   256
#define Hh   128
#define Wwid 128
#define HW   16384
#define CHW  4194304      // 256*128*128
#define Bb   8
#define Gg   64
#define NBLK 128          // stats partial blocks per sample

// ---------------- static scratch (no allocations allowed) ----------------
__device__ float  g_bufA[(size_t)Bb * CHW];
__device__ float  g_bufB[(size_t)Bb * CHW];
__device__ float  g_bufC[(size_t)Bb * CHW];
__device__ float  g_bufX1[(size_t)Bb * CHW];
__device__ double g_part[Bb * NBLK * 2];
__device__ float  g_ppart[Bb * Cc * 64];   // pooled partials: [b][c][blk]
__device__ float  g_scale[Bb * Cc];
__device__ float  g_shift[Bb * Cc];
__device__ float  g_att[Bb * Cc];

__device__ __forceinline__ float gelu1(float x) {
    return 0.5f * x * (1.0f + erff(x * 0.70710678118654752440f));
}

// ---------------- per-sample mean/var partials ----------------
__global__ void __launch_bounds__(256) stats1_k(const float* __restrict__ in,
                                                double* __restrict__ part) {
    int b = blockIdx.y, blk = blockIdx.x, t = threadIdx.x;
    size_t base = (size_t)b * CHW + (size_t)blk * (CHW / NBLK);
    double s = 0.0, s2 = 0.0;
    for (int i = t; i < CHW / NBLK; i += 256) {
        float x = in[base + i];
        s  += (double)x;
        s2 += (double)x * (double)x;
    }
    __shared__ double ss[256], ss2[256];
    ss[t] = s; ss2[t] = s2;
    __syncthreads();
    for (int off = 128; off > 0; off >>= 1) {
        if (t < off) { ss[t] += ss[t + off]; ss2[t] += ss2[t + off]; }
        __syncthreads();
    }
    if (t == 0) {
        part[(b * NBLK + blk) * 2 + 0] = ss[0];
        part[(b * NBLK + blk) * 2 + 1] = ss2[0];
    }
}

// reduce partials -> per-(b,c) affine scale/shift folding GN into the next conv
__global__ void __launch_bounds__(256) stats2_k(const double* __restrict__ part,
                                                const float* __restrict__ gw,
                                                const float* __restrict__ gb,
                                                float* __restrict__ scale,
                                                float* __restrict__ shift) {
    int b = blockIdx.x, t = threadIdx.x;
    __shared__ double ss[128], ss2[128];
    __shared__ float smean, srstd;
    if (t < 128) {
        ss[t]  = part[(b * NBLK + t) * 2 + 0];
        ss2[t] = part[(b * NBLK + t) * 2 + 1];
    }
    __syncthreads();
    for (int off = 64; off > 0; off >>= 1) {
        if (t < off) { ss[t] += ss[t + off]; ss2[t] += ss2[t + off]; }
        __syncthreads();
    }
    if (t == 0) {
        double m   = ss[0] / (double)CHW;
        double var = ss2[0] / (double)CHW - m * m;
        smean = (float)m;
        srstd = rsqrtf((float)var + 1e-5f);
    }
    __syncthreads();
    float sc = srstd * gw[t];
    scale[b * Cc + t] = sc;
    shift[b * Cc + t] = gb[t] - smean * sc;
}

// ---------------- conv 1x1 as GEMM: out[o,p] = sum_c W[o,c] * T(in[c,p]) ----
// T(x) = x*scale[b,c] + shift[b,c]  (GN / attention folded into input load)
// epi 0: out = y + bias[o]
// epi 1: out = (y + bias[o]) * echan[o] + res[b,o,p]
__global__ void __launch_bounds__(256) conv1x1_k(
    const float* __restrict__ in, const float* __restrict__ W,
    const float* __restrict__ bias, float* __restrict__ out,
    const float* __restrict__ tscale, const float* __restrict__ tshift,
    int epi, const float* __restrict__ echan, const float* __restrict__ res) {

    __shared__ float As[16][136];   // A transposed: As[k][o], padded
    __shared__ float Bs[16][68];    // Bs[k][p]
    __shared__ float sSc[256], sSh[256];

    int t  = threadIdx.x;
    int b  = blockIdx.z;
    int o0 = blockIdx.y * 128;
    int p0 = blockIdx.x * 64;
    size_t ibase = (size_t)b * CHW;

    if (tscale) {
        sSc[t] = tscale[b * Cc + t];
        sSh[t] = tshift ? tshift[b * Cc + t] : 0.f;
    } else {
        sSc[t] = 1.f; sSh[t] = 0.f;
    }
    __syncthreads();

    int tx = t & 15, ty = t >> 4;
    float acc[8][4];
#pragma unroll
    for (int i = 0; i < 8; i++)
#pragma unroll
        for (int j = 0; j < 4; j++) acc[i][j] = 0.f;

    for (int kc = 0; kc < 256; kc += 16) {
        // load W tile [128 o x 16 k], transposed into As[k][o]
#pragma unroll
        for (int i = 0; i < 8; i++) {
            int idx = i * 256 + t;
            int o = idx >> 4, k = idx & 15;
            As[k][o] = W[(size_t)(o0 + o) * 256 + kc + k];
        }
        // load input tile [16 k x 64 p], with per-channel affine transform
        {
            int k  = t >> 4;
            int px = (t & 15) << 2;
            const float4 v = *(const float4*)(in + ibase + (size_t)(kc + k) * HW + p0 + px);
            float sc = sSc[kc + k], sh = sSh[kc + k];
            Bs[k][px + 0] = v.x * sc + sh;
            Bs[k][px + 1] = v.y * sc + sh;
            Bs[k][px + 2] = v.z * sc + sh;
            Bs[k][px + 3] = v.w * sc + sh;
        }
        __syncthreads();
#pragma unroll
        for (int k = 0; k < 16; k++) {
            float a[8], bv[4];
#pragma unroll
            for (int i = 0; i < 8; i++) a[i] = As[k][ty * 8 + i];
#pragma unroll
            for (int j = 0; j < 4; j++) bv[j] = Bs[k][tx * 4 + j];
#pragma unroll
            for (int i = 0; i < 8; i++)
#pragma unroll
                for (int j = 0; j < 4; j++) acc[i][j] += a[i] * bv[j];
        }
        __syncthreads();
    }

    int p = p0 + tx * 4;
#pragma unroll
    for (int i = 0; i < 8; i++) {
        int o = o0 + ty * 8 + i;
        float bo = __ldg(&bias[o]);
        size_t oidx = ibase + (size_t)o * HW + p;
        float4 y;
        y.x = acc[i][0] + bo; y.y = acc[i][1] + bo;
        y.z = acc[i][2] + bo; y.w = acc[i][3] + bo;
        if (epi == 1) {
            float e = __ldg(&echan[o]);
            float4 r = *(const float4*)(res + oidx);
            y.x = y.x * e + r.x; y.y = y.y * e + r.y;
            y.z = y.z * e + r.z; y.w = y.w * e + r.w;
        }
        *(float4*)(out + oidx) = y;
    }
}

// ---------------- depthwise 3x3 (SAME, zero pad) + bias ----------------
__global__ void __launch_bounds__(256) dw3x3_k(const float* __restrict__ in,
                                               const float* __restrict__ w2,
                                               const float* __restrict__ b2,
                                               float* __restrict__ out) {
    __shared__ float s[34][128];
    int t = threadIdx.x;
    int b = blockIdx.z, c = blockIdx.y;
    int r0 = blockIdx.x * 32;
    size_t base = (size_t)b * CHW + (size_t)c * HW;

#pragma unroll
    for (int it = 0; it < 17; it++) {
        int idx = it * 256 + t;          // 0..4351 == 34*128
        int rr = idx >> 7, cc = idx & 127;
        int gr = r0 - 1 + rr;
        s[rr][cc] = (gr >= 0 && gr < Hh) ? in[base + (size_t)gr * Wwid + cc] : 0.f;
    }
    float wv[9];
#pragma unroll
    for (int i = 0; i < 9; i++) wv[i] = __ldg(&w2[c * 9 + i]);
    float bias = __ldg(&b2[c]);
    __syncthreads();

#pragma unroll
    for (int it = 0; it < 16; it++) {
        int idx = it * 256 + t;
        int r = idx >> 7, cc = idx & 127;
        int sr = r + 1;                  // smem row of the output pixel
        float sum = bias;
#pragma unroll
        for (int dy = 0; dy < 3; dy++) {
            float l = (cc > 0)   ? s[sr - 1 + dy][cc - 1] : 0.f;
            float m = s[sr - 1 + dy][cc];
            float rr = (cc < 127) ? s[sr - 1 + dy][cc + 1] : 0.f;
            sum += wv[dy * 3 + 0] * l + wv[dy * 3 + 1] * m + wv[dy * 3 + 2] * rr;
        }
        out[base + (size_t)(r0 + r) * Wwid + cc] = sum;
    }
}

// ------ gelu(gelu(.)) + grouped 1x1 (64 groups of 4) + optional pooled partials
__global__ void __launch_bounds__(256) grouped_k(const float* __restrict__ in,
                                                 const float* __restrict__ wg,
                                                 const float* __restrict__ bg,
                                                 float* __restrict__ out,
                                                 float* __restrict__ ppart) {
    int t = threadIdx.x;
    int b = blockIdx.z, g = blockIdx.y;
    int p = blockIdx.x * 256 + t;
    size_t base = (size_t)b * CHW + (size_t)(g * 4) * HW + p;

    float v[4];
#pragma unroll
    for (int i = 0; i < 4; i++) {
        float x = in[base + (size_t)i * HW];
        v[i] = gelu1(gelu1(x));
    }
    float u[4];
#pragma unroll
    for (int o = 0; o < 4; o++) {
        float s = __ldg(&bg[g * 4 + o]);
#pragma unroll
        for (int i = 0; i < 4; i++) s += __ldg(&wg[g * 16 + o * 4 + i]) * v[i];
        u[o] = s;
        out[base + (size_t)o * HW] = s;
    }
    if (ppart) {
        __shared__ float red[8];
#pragma unroll
        for (int o = 0; o < 4; o++) {
            float val = u[o];
#pragma unroll
            for (int off = 16; off > 0; off >>= 1)
                val += __shfl_down_sync(0xffffffffu, val, off);
            if ((t & 31) == 0) red[t >> 5] = val;
            __syncthreads();
            if (t < 8) {
                float v2 = red[t];
#pragma unroll
                for (int off = 4; off > 0; off >>= 1)
                    v2 += __shfl_down_sync(0xffu, v2, off);
                if (t == 0)
                    ppart[((size_t)b * Cc + g * 4 + o) * 64 + blockIdx.x] = v2;
            }
            __syncthreads();
        }
    }
}

// ------ channel attention: att[b,o] = b_sca[o] + sum_c mean_hw(x1)[b,c]*w_sca[o,c]
__global__ void __launch_bounds__(256) att_k(const float* __restrict__ ppart,
                                             const float* __restrict__ wsca,
                                             const float* __restrict__ bsca,
                                             float* __restrict__ att) {
    __shared__ float sp[256];
    int b = blockIdx.x, t = threadIdx.x;
    float s = 0.f;
    const float* pr = ppart + ((size_t)b * Cc + t) * 64;
#pragma unroll 8
    for (int j = 0; j < 64; j++) s += pr[j];
    sp[t] = s * (1.f / (float)HW);
    __syncthreads();
    float acc = __ldg(&bsca[t]);
    const float* wrow = wsca + (size_t)t * 256;
    for (int c = 0; c < 256; c++) acc += sp[c] * __ldg(&wrow[c]);
    att[b * Cc + t] = acc;
}

// ---------------- launch ----------------
extern "C" void kernel_launch(void* const* d_in, const int* in_sizes, int n_in,
                              void* d_out, int out_size) {
    const float* x     = (const float*)d_in[0];
    const float* gn1_w = (const float*)d_in[1];
    const float* gn1_b = (const float*)d_in[2];
    const float* w1    = (const float*)d_in[3];
    const float* b1    = (const float*)d_in[4];
    const float* w2    = (const float*)d_in[5];
    const float* b2    = (const float*)d_in[6];
    const float* wg1   = (const float*)d_in[7];
    const float* bg1   = (const float*)d_in[8];
    const float* w_sca = (const float*)d_in[9];
    const float* b_sca = (const float*)d_in[10];
    const float* w3    = (const float*)d_in[11];
    const float* b3    = (const float*)d_in[12];
    const float* gn2_w = (const float*)d_in[13];
    const float* gn2_b = (const float*)d_in[14];
    const float* w4    = (const float*)d_in[15];
    const float* b4    = (const float*)d_in[16];
    const float* wg2   = (const float*)d_in[17];
    const float* bg2   = (const float*)d_in[18];
    const float* w5    = (const float*)d_in[19];
    const float* b5    = (const float*)d_in[20];
    const float* beta  = (const float*)d_in[21];
    const float* gamma = (const float*)d_in[22];
    float* out = (float*)d_out;

    float *bufA, *bufB, *bufC, *bufX1, *ppart, *scl, *shf, *attv;
    double* part;
    cudaGetSymbolAddress((void**)&bufA,  g_bufA);
    cudaGetSymbolAddress((void**)&bufB,  g_bufB);
    cudaGetSymbolAddress((void**)&bufC,  g_bufC);
    cudaGetSymbolAddress((void**)&bufX1, g_bufX1);
    cudaGetSymbolAddress((void**)&part,  g_part);
    cudaGetSymbolAddress((void**)&ppart, g_ppart);
    cudaGetSymbolAddress((void**)&scl,   g_scale);
    cudaGetSymbolAddress((void**)&shf,   g_shift);
    cudaGetSymbolAddress((void**)&attv,  g_att);

    dim3 cgrid(HW / 64, 2, Bb);     // conv GEMM
    dim3 ggrid(HW / 256, Gg, Bb);   // grouped 1x1
    dim3 dgrid(4, Cc, Bb);          // dwconv 3x3
    dim3 sgrid(NBLK, Bb);           // stats partials

    // ---- path 1 ----
    stats1_k<<<sgrid, 256>>>(x, part);
    stats2_k<<<Bb, 256>>>(part, gn1_w, gn1_b, scl, shf);
    conv1x1_k<<<cgrid, 256>>>(x, w1, b1, bufA, scl, shf, 0, nullptr, nullptr);
    dw3x3_k<<<dgrid, 256>>>(bufA, w2, b2, bufB);
    grouped_k<<<ggrid, 256>>>(bufB, wg1, bg1, bufC, ppart);
    att_k<<<Bb, 256>>>(ppart, w_sca, b_sca, attv);
    // x1 = (W3 @ (att*bufC) + b3) * beta + x
    conv1x1_k<<<cgrid, 256>>>(bufC, w3, b3, bufX1, attv, nullptr, 1, beta, x);

    // ---- path 2 ----
    stats1_k<<<sgrid, 256>>>(bufX1, part);
    stats2_k<<<Bb, 256>>>(part, gn2_w, gn2_b, scl, shf);
    conv1x1_k<<<cgrid, 256>>>(bufX1, w4, b4, bufA, scl, shf, 0, nullptr, nullptr);
    grouped_k<<<ggrid, 256>>>(bufA, wg2, bg2, bufB, nullptr);
    // out = (W5 @ bufB + b5) * gamma + x1
    conv1x1_k<<<cgrid, 256>>>(bufB, w5, b5, out, nullptr, nullptr, 1, gamma, bufX1);
}